// round 1
// baseline (speedup 1.0000x reference)
#include <cuda_runtime.h>
#include <cuda_bf16.h>
#include <cstdint>
#include <math.h>

// Problem constants
#define BB    256
#define DD    2048
#define PP    8192
#define NPP   8
#define NCAMS 8
#define BGKNN 40
#define KPOS  3
#define MTOT  512   // 256 feature rows + 256 gathered memory rows

// GEMM tiling
#define BM 128
#define BN 128
#define BKK 64
#define STAGES 3
#define STAGE_BYTES (2 * BM * BKK * 2)        // A tile + B tile, bf16: 32768
#define GEMM_SMEM (STAGES * STAGE_BYTES)      // 98304

// ---------------- workspaces (static device memory; no allocs) ----------------
__device__ __align__(16) __nv_bfloat16 g_A[MTOT * DD];     // 2 MB
__device__ __align__(16) __nv_bfloat16 g_Bm[PP * DD];      // 32 MB
__device__ float g_score[BB * PP];                         // 8 MB  (raw dot, x10 applied later)
__device__ float g_sims[BB * PP];                          // 8 MB
__device__ int   g_pt[BB];
__device__ int   g_py[BB];
__device__ int   g_camArr[BB];
__device__ float g_Loff[BB];
__device__ float g_Lon[BB];

// ---------------- small prep kernels ----------------
__global__ void prep_meta_kernel(const int* __restrict__ targets,
                                 const int* __restrict__ apl) {
    int i = threadIdx.x;
    if (i < BB) {
        int pt = apl[targets[i]];
        g_pt[i] = pt;
        g_py[i] = pt / NPP;
        g_camArr[i] = pt % NCAMS;
    }
}

__global__ void convB_kernel(const float* __restrict__ gm) {
    int idx = blockIdx.x * blockDim.x + threadIdx.x;   // float4 index
    if (idx < PP * DD / 4) {
        float4 v = ((const float4*)gm)[idx];
        union { __nv_bfloat16 h[4]; uint2 u; } tmp;
        tmp.h[0] = __float2bfloat16(v.x);
        tmp.h[1] = __float2bfloat16(v.y);
        tmp.h[2] = __float2bfloat16(v.z);
        tmp.h[3] = __float2bfloat16(v.w);
        ((uint2*)g_Bm)[idx] = tmp.u;
    }
}

__global__ void buildA_kernel(const float* __restrict__ feats,
                              const float* __restrict__ gm) {
    int idx = blockIdx.x * blockDim.x + threadIdx.x;   // float4 index over 512*2048/4
    if (idx < MTOT * DD / 4) {
        int r  = idx / (DD / 4);
        int k4 = idx % (DD / 4);
        float4 v;
        if (r < BB) v = ((const float4*)(feats + (size_t)r * DD))[k4];
        else        v = ((const float4*)(gm + (size_t)g_pt[r - BB] * DD))[k4];
        union { __nv_bfloat16 h[4]; uint2 u; } tmp;
        tmp.h[0] = __float2bfloat16(v.x);
        tmp.h[1] = __float2bfloat16(v.y);
        tmp.h[2] = __float2bfloat16(v.z);
        tmp.h[3] = __float2bfloat16(v.w);
        ((uint2*)g_A)[idx] = tmp.u;
    }
}

// ---------------- GEMM: C[512,8192] = A[512,2048] * B[8192,2048]^T ----------------
__global__ __launch_bounds__(256) void gemm_kernel() {
    extern __shared__ char smem[];
    const unsigned smemB = (unsigned)__cvta_generic_to_shared(smem);
    const int t = threadIdx.x;
    const int lane = t & 31, warp = t >> 5;
    const int wm = warp & 3;   // 4 m-warps (32 rows each)
    const int wn = warp >> 2;  // 2 n-warps (64 cols each)
    const int bn = blockIdx.x, bm = blockIdx.y;

    float acc[2][8][4];
#pragma unroll
    for (int i = 0; i < 2; i++)
#pragma unroll
        for (int j = 0; j < 8; j++)
#pragma unroll
            for (int k = 0; k < 4; k++) acc[i][j][k] = 0.f;

    const __nv_bfloat16* gA = g_A  + (size_t)bm * BM * DD;
    const __nv_bfloat16* gB = g_Bm + (size_t)bn * BN * DD;

    auto loadStage = [&](int s, int kt) {
        unsigned sA = smemB + s * STAGE_BYTES;
        unsigned sB = sA + BM * BKK * 2;
#pragma unroll
        for (int i = 0; i < 4; i++) {
            int c = t + i * 256;          // chunk 0..1023 (128 rows x 8 x 16B)
            int row = c >> 3, kc = c & 7;
            unsigned dA = sA + row * 128 + ((kc ^ (row & 7)) << 4);
            const void* srcA = gA + (size_t)row * DD + kt * BKK + kc * 8;
            asm volatile("cp.async.cg.shared.global [%0], [%1], 16;\n" ::"r"(dA), "l"(srcA));
            unsigned dB = sB + row * 128 + ((kc ^ (row & 7)) << 4);
            const void* srcB = gB + (size_t)row * DD + kt * BKK + kc * 8;
            asm volatile("cp.async.cg.shared.global [%0], [%1], 16;\n" ::"r"(dB), "l"(srcB));
        }
        asm volatile("cp.async.commit_group;\n");
    };

    const int KT = DD / BKK;   // 32
    for (int s = 0; s < STAGES - 1; s++) loadStage(s, s);

    for (int kt = 0; kt < KT; kt++) {
        asm volatile("cp.async.wait_group %0;\n" ::"n"(STAGES - 2));
        __syncthreads();
        int nk = kt + STAGES - 1;
        if (nk < KT) loadStage(nk % STAGES, nk);
        else asm volatile("cp.async.commit_group;\n");

        int s = kt % STAGES;
        unsigned sA = smemB + s * STAGE_BYTES;
        unsigned sB = sA + BM * BKK * 2;
#pragma unroll
        for (int ks = 0; ks < 4; ks++) {
            unsigned af[2][4];
#pragma unroll
            for (int mt = 0; mt < 2; mt++) {
                int row = wm * 32 + mt * 16 + (lane & 15);
                int cch = ks * 2 + (lane >> 4);
                unsigned ad = sA + row * 128 + ((cch ^ (row & 7)) << 4);
                asm volatile("ldmatrix.sync.aligned.m8n8.x4.shared.b16 {%0,%1,%2,%3}, [%4];\n"
                             : "=r"(af[mt][0]), "=r"(af[mt][1]), "=r"(af[mt][2]), "=r"(af[mt][3])
                             : "r"(ad));
            }
            unsigned bq[4][4];
#pragma unroll
            for (int pr = 0; pr < 4; pr++) {
                int row = wn * 64 + pr * 16 + (lane & 7) + ((lane & 16) >> 1);
                int cch = ks * 2 + ((lane >> 3) & 1);
                unsigned ad = sB + row * 128 + ((cch ^ (row & 7)) << 4);
                asm volatile("ldmatrix.sync.aligned.m8n8.x4.shared.b16 {%0,%1,%2,%3}, [%4];\n"
                             : "=r"(bq[pr][0]), "=r"(bq[pr][1]), "=r"(bq[pr][2]), "=r"(bq[pr][3])
                             : "r"(ad));
            }
#pragma unroll
            for (int mt = 0; mt < 2; mt++)
#pragma unroll
                for (int nt = 0; nt < 8; nt++) {
                    unsigned b0 = bq[nt >> 1][(nt & 1) * 2];
                    unsigned b1 = bq[nt >> 1][(nt & 1) * 2 + 1];
                    asm volatile(
                        "mma.sync.aligned.m16n8k16.row.col.f32.bf16.bf16.f32 "
                        "{%0,%1,%2,%3}, {%4,%5,%6,%7}, {%8,%9}, {%0,%1,%2,%3};\n"
                        : "+f"(acc[mt][nt][0]), "+f"(acc[mt][nt][1]),
                          "+f"(acc[mt][nt][2]), "+f"(acc[mt][nt][3])
                        : "r"(af[mt][0]), "r"(af[mt][1]), "r"(af[mt][2]), "r"(af[mt][3]),
                          "r"(b0), "r"(b1));
                }
        }
    }

    // epilogue: rows 0-255 -> g_score, rows 256-511 -> g_sims (bm is tile of 128)
    float* outBase = (bm < 2) ? (g_score + (size_t)bm * BM * PP)
                              : (g_sims + (size_t)(bm - 2) * BM * PP);
    int g = lane >> 2, tg = lane & 3;
#pragma unroll
    for (int mt = 0; mt < 2; mt++) {
        int m0 = wm * 32 + mt * 16 + g;
#pragma unroll
        for (int nt = 0; nt < 8; nt++) {
            int n = bn * BN + wn * 64 + nt * 8 + tg * 2;
            *(float2*)(outBase + (size_t)m0 * PP + n) =
                make_float2(acc[mt][nt][0], acc[mt][nt][1]);
            *(float2*)(outBase + (size_t)(m0 + 8) * PP + n) =
                make_float2(acc[mt][nt][2], acc[mt][nt][3]);
        }
    }
}

// ---------------- radix top-K helpers ----------------
__device__ __forceinline__ unsigned f2key(float v) {
    unsigned u = __float_as_uint(v);
    return (u & 0x80000000u) ? ~u : (u | 0x80000000u);
}
__device__ __forceinline__ float key2f(unsigned u) {
    unsigned b = (u & 0x80000000u) ? (u ^ 0x80000000u) : ~u;
    return __uint_as_float(b);
}

// Finds threshold T and `need` (# of ==T elements to take) such that
// top-K = {key > T} plus first `need` keys == T. 256 threads assumed.
__device__ void radix_topk(const unsigned* keys, int K, unsigned* hist,
                           unsigned* sh, unsigned& T, int& need) {
    const int t = threadIdx.x;
    unsigned prefix = 0;
    int rem = K;
    for (int pass = 0; pass < 4; pass++) {
        const int shift = 24 - 8 * pass;
        hist[t] = 0;
        __syncthreads();
        unsigned mask = pass ? (0xFFFFFFFFu << (shift + 8)) : 0u;
        for (int p = t; p < PP; p += 256) {
            unsigned u = keys[p];
            if ((u & mask) == prefix) atomicAdd(&hist[(u >> shift) & 255u], 1u);
        }
        __syncthreads();
        if (t == 0) {
            unsigned c = 0;
            int d;
            for (d = 255; d >= 0; d--) { c += hist[d]; if ((int)c >= rem) break; }
            if (d < 0) d = 0;
            unsigned cgt = c - hist[d];
            sh[0] = prefix | ((unsigned)d << shift);
            sh[1] = (unsigned)(rem - (int)cgt);
        }
        __syncthreads();
        prefix = sh[0];
        rem = (int)sh[1];
        __syncthreads();
    }
    T = prefix;
    need = rem;
}

// ---------------- offline loss ----------------
__global__ __launch_bounds__(256) void loss_off_kernel() {
    __shared__ unsigned keys[PP];
    __shared__ unsigned hist[256];
    __shared__ float list[BGKNN];
    __shared__ unsigned sh[4];   // 0:prefix 1:need 2:eqcnt 3:outcnt
    const int row = blockIdx.x, t = threadIdx.x;
    const float* src = g_score + (size_t)row * PP;
    const int p0 = g_py[row] * NPP;

    for (int p = t; p < PP; p += 256) {
        unsigned u = f2key(src[p]);
        keys[p] = ((unsigned)(p - p0) < 8u) ? 0u : u;  // mask positives
    }
    __syncthreads();

    unsigned T; int need;
    radix_topk(keys, BGKNN, hist, sh, T, need);
    if (t == 0) { sh[2] = 0; sh[3] = 0; }
    __syncthreads();

    for (int p = t; p < PP; p += 256) {
        unsigned u = keys[p];
        if (u > T) {
            unsigned s = atomicAdd(&sh[3], 1u);
            list[s] = key2f(u);
        } else if (u == T) {
            unsigned e = atomicAdd(&sh[2], 1u);
            if (e < (unsigned)need) {
                unsigned s = atomicAdd(&sh[3], 1u);
                list[s] = key2f(u);
            }
        }
    }
    __syncthreads();

    if (t == 0) {
        float pos[NPP];
        float m = -1e30f;
        for (int j = 0; j < NPP; j++) {
            pos[j] = src[p0 + j] * 10.0f;
            m = fmaxf(m, pos[j]);
        }
        for (int j = 0; j < BGKNN; j++) m = fmaxf(m, list[j] * 10.0f);
        float se = 0.f, ps = 0.f;
        for (int j = 0; j < BGKNN; j++) se += expf(list[j] * 10.0f - m);
        for (int j = 0; j < NPP; j++) { se += expf(pos[j] - m); ps += pos[j]; }
        g_Loff[row] = m + logf(se) - ps * (1.0f / NPP);
    }
}

// ---------------- online loss ----------------
__global__ __launch_bounds__(256) void loss_on_kernel() {
    __shared__ unsigned keys[PP];
    __shared__ unsigned hist[256];
    __shared__ unsigned ckey[256];
    __shared__ int cid[256];
    __shared__ int idxList[BGKNN];
    __shared__ int boost[KPOS];
    __shared__ unsigned sh[4];
    const int row = blockIdx.x, t = threadIdx.x;
    const float* ssrc = g_sims + (size_t)row * PP;

    // Load keys + camera-wise local argmax. Thread t only sees cam = t&7
    // (stride 256 is a multiple of 8). Ascending p keeps lowest id on ties.
    unsigned bk = 0;
    int bi = 0x7fffffff;
    for (int p = t; p < PP; p += 256) {
        unsigned u = f2key(ssrc[p]);
        keys[p] = u;
        if (u > bk) { bk = u; bi = p >> 3; }
    }
    ckey[t] = bk;
    cid[t] = bi;
    __syncthreads();
    for (int s = 128; s >= 8; s >>= 1) {
        if (t < s) {
            unsigned ok = ckey[t + s]; int oi = cid[t + s];
            if (ok > ckey[t] || (ok == ckey[t] && oi < cid[t])) { ckey[t] = ok; cid[t] = oi; }
        }
        __syncthreads();
    }
    // entries 0..7 now hold per-camera (max key, id); cam == index.

    if (t == 0) {
        bool used[NCAMS] = {false, false, false, false, false, false, false, false};
        for (int j = 0; j < KPOS; j++) {
            int bc = -1; unsigned bv = 0;
            for (int c = 0; c < NCAMS; c++)
                if (!used[c] && (bc < 0 || ckey[c] > bv)) { bc = c; bv = ckey[c]; }
            used[bc] = true;
            int proxy = cid[bc] * NCAMS + bc;
            boost[j] = proxy;
            keys[proxy] = 0u;   // exclude from background top-40
        }
    }
    __syncthreads();

    unsigned T; int need;
    radix_topk(keys, BGKNN, hist, sh, T, need);
    if (t == 0) { sh[2] = 0; sh[3] = 0; }
    __syncthreads();

    for (int p = t; p < PP; p += 256) {
        unsigned u = keys[p];
        if (u > T) {
            unsigned s = atomicAdd(&sh[3], 1u);
            idxList[s] = p;
        } else if (u == T) {
            unsigned e = atomicAdd(&sh[2], 1u);
            if (e < (unsigned)need) {
                unsigned s = atomicAdd(&sh[3], 1u);
                idxList[s] = p;
            }
        }
    }
    __syncthreads();

    if (t == 0) {
        const float* inp = g_score + (size_t)row * PP;  // values gathered from inputs!
        float v[BGKNN + KPOS];
        float m = -1e30f;
        for (int j = 0; j < BGKNN; j++) {
            v[j] = inp[idxList[j]] * 10.0f;
            m = fmaxf(m, v[j]);
        }
        float ps = 0.f;
        for (int j = 0; j < KPOS; j++) {
            float x = inp[boost[j]] * 10.0f;
            v[BGKNN + j] = x;
            ps += x;
            m = fmaxf(m, x);
        }
        float se = 0.f;
        for (int j = 0; j < BGKNN + KPOS; j++) se += expf(v[j] - m);
        g_Lon[row] = m + logf(se) - ps * (1.0f / KPOS);
    }
}

// ---------------- final per-camera reduction ----------------
__global__ void finalize_kernel(float* out) {
    if (threadIdx.x == 0) {
        float offs[NCAMS] = {}, ons[NCAMS] = {};
        int cnt[NCAMS] = {};
        for (int i = 0; i < BB; i++) {
            int c = g_camArr[i];
            offs[c] += g_Loff[i];
            ons[c] += g_Lon[i];
            cnt[c]++;
        }
        float loss = 0.f;
        for (int c = 0; c < NCAMS; c++)
            if (cnt[c] > 0) loss += offs[c] / cnt[c] + ons[c] / cnt[c];
        out[0] = loss;
    }
}

// ---------------- launch ----------------
extern "C" void kernel_launch(void* const* d_in, const int* in_sizes, int n_in,
                              void* d_out, int out_size) {
    const float* features = (const float*)d_in[0];
    const float* gmemory  = (const float*)d_in[1];
    const int*   targets  = (const int*)d_in[2];
    const int*   apl      = (const int*)d_in[3];
    float* out = (float*)d_out;

    prep_meta_kernel<<<1, 256>>>(targets, apl);
    convB_kernel<<<(PP * DD / 4 + 255) / 256, 256>>>(gmemory);
    buildA_kernel<<<(MTOT * DD / 4 + 255) / 256, 256>>>(features, gmemory);

    cudaFuncSetAttribute(gemm_kernel, cudaFuncAttributeMaxDynamicSharedMemorySize,
                         GEMM_SMEM);
    gemm_kernel<<<dim3(PP / BN, MTOT / BM), 256, GEMM_SMEM>>>();

    loss_off_kernel<<<BB, 256>>>();
    loss_on_kernel<<<BB, 256>>>();
    finalize_kernel<<<1, 32>>>(out);
}

// round 4
// speedup vs baseline: 1.4695x; 1.4695x over previous
#include <cuda_runtime.h>
#include <cuda_bf16.h>
#include <cstdint>
#include <math.h>

// Problem constants
#define BB    256
#define DD    2048
#define PP    8192
#define NPP   8
#define NCAMS 8
#define BGKNN 40
#define KPOS  3
#define MTOT  512   // 256 feature rows + 256 gathered memory rows

// GEMM tiling
#define BM 128
#define BN 128
#define BKK 64
#define STAGES 3
#define STAGE_BYTES (2 * BM * BKK * 2)        // A tile + B tile, bf16: 32768
#define GEMM_SMEM (STAGES * STAGE_BYTES)      // 98304  (2 CTAs/SM: 196KB <= 228KB)

// ---------------- workspaces (static device memory; no allocs) ----------------
__device__ __align__(16) __nv_bfloat16 g_A[MTOT * DD];     // 2 MB
__device__ __align__(16) __nv_bfloat16 g_Bm[PP * DD];      // 32 MB
__device__ float g_score[(size_t)BB * PP];                 // 8 MB (raw dot; x10 in loss)
__device__ float g_sims [(size_t)BB * PP];                 // 8 MB
__device__ int   g_pt[BB], g_py[BB], g_camArr[BB];
__device__ float g_Loff[BB], g_Lon[BB];

// ---------------- small prep kernels ----------------
__global__ void prep_meta_kernel(const int* __restrict__ targets,
                                 const int* __restrict__ apl) {
    int i = threadIdx.x;
    if (i < BB) {
        int pt = apl[targets[i]];
        g_pt[i] = pt;
        g_py[i] = pt / NPP;
        g_camArr[i] = pt % NCAMS;
    }
}

__global__ void convB_kernel(const float* __restrict__ gm) {
    int idx = blockIdx.x * blockDim.x + threadIdx.x;   // float4 index
    if (idx < PP * DD / 4) {
        float4 v = ((const float4*)gm)[idx];
        union { __nv_bfloat16 h[4]; uint2 u; } tmp;
        tmp.h[0] = __float2bfloat16(v.x);
        tmp.h[1] = __float2bfloat16(v.y);
        tmp.h[2] = __float2bfloat16(v.z);
        tmp.h[3] = __float2bfloat16(v.w);
        ((uint2*)g_Bm)[idx] = tmp.u;
    }
}

__global__ void buildA_kernel(const float* __restrict__ feats,
                              const float* __restrict__ gm) {
    int idx = blockIdx.x * blockDim.x + threadIdx.x;   // float4 index over 512*2048/4
    if (idx < MTOT * DD / 4) {
        int r  = idx / (DD / 4);
        int k4 = idx % (DD / 4);
        float4 v;
        if (r < BB) v = ((const float4*)(feats + (size_t)r * DD))[k4];
        else        v = ((const float4*)(gm + (size_t)g_pt[r - BB] * DD))[k4];
        union { __nv_bfloat16 h[4]; uint2 u; } tmp;
        tmp.h[0] = __float2bfloat16(v.x);
        tmp.h[1] = __float2bfloat16(v.y);
        tmp.h[2] = __float2bfloat16(v.z);
        tmp.h[3] = __float2bfloat16(v.w);
        ((uint2*)g_A)[idx] = tmp.u;
    }
}

// ---------------- GEMM: C[512,8192] = A[512,2048] * B[8192,2048]^T ----------------
// __launch_bounds__(256, 2): cap regs at 128 so 2 CTAs (16 warps) co-reside per SM.
__global__ __launch_bounds__(256, 2) void gemm_kernel() {
    extern __shared__ char smem[];
    const unsigned smemB = (unsigned)__cvta_generic_to_shared(smem);
    const int t = threadIdx.x;
    const int lane = t & 31, warp = t >> 5;
    const int wm = warp & 3;   // 4 m-warps (32 rows each)
    const int wn = warp >> 2;  // 2 n-warps (64 cols each)
    const int bn = blockIdx.x, bm = blockIdx.y;

    float acc[2][8][4];
#pragma unroll
    for (int i = 0; i < 2; i++)
#pragma unroll
        for (int j = 0; j < 8; j++)
#pragma unroll
            for (int k = 0; k < 4; k++) acc[i][j][k] = 0.f;

    const __nv_bfloat16* gA = g_A  + (size_t)bm * BM * DD;
    const __nv_bfloat16* gB = g_Bm + (size_t)bn * BN * DD;

    auto loadStage = [&](int s, int kt) {
        unsigned sA = smemB + s * STAGE_BYTES;
        unsigned sB = sA + BM * BKK * 2;
#pragma unroll
        for (int i = 0; i < 4; i++) {
            int c = t + i * 256;          // chunk 0..1023 (128 rows x 8 x 16B)
            int row = c >> 3, kc = c & 7;
            unsigned dA = sA + row * 128 + ((kc ^ (row & 7)) << 4);
            const void* srcA = gA + (size_t)row * DD + kt * BKK + kc * 8;
            asm volatile("cp.async.cg.shared.global [%0], [%1], 16;\n" ::"r"(dA), "l"(srcA));
            unsigned dB = sB + row * 128 + ((kc ^ (row & 7)) << 4);
            const void* srcB = gB + (size_t)row * DD + kt * BKK + kc * 8;
            asm volatile("cp.async.cg.shared.global [%0], [%1], 16;\n" ::"r"(dB), "l"(srcB));
        }
        asm volatile("cp.async.commit_group;\n");
    };

    const int KT = DD / BKK;   // 32
    for (int s = 0; s < STAGES - 1; s++) loadStage(s, s);

    for (int kt = 0; kt < KT; kt++) {
        asm volatile("cp.async.wait_group %0;\n" ::"n"(STAGES - 2));
        __syncthreads();
        int nk = kt + STAGES - 1;
        if (nk < KT) loadStage(nk % STAGES, nk);
        else asm volatile("cp.async.commit_group;\n");

        int s = kt % STAGES;
        unsigned sA = smemB + s * STAGE_BYTES;
        unsigned sB = sA + BM * BKK * 2;
#pragma unroll
        for (int ks = 0; ks < 4; ks++) {
            unsigned af[2][4];
#pragma unroll
            for (int mt = 0; mt < 2; mt++) {
                int row = wm * 32 + mt * 16 + (lane & 15);
                int cch = ks * 2 + (lane >> 4);
                unsigned ad = sA + row * 128 + ((cch ^ (row & 7)) << 4);
                asm volatile("ldmatrix.sync.aligned.m8n8.x4.shared.b16 {%0,%1,%2,%3}, [%4];\n"
                             : "=r"(af[mt][0]), "=r"(af[mt][1]), "=r"(af[mt][2]), "=r"(af[mt][3])
                             : "r"(ad));
            }
            unsigned bq[4][4];
#pragma unroll
            for (int pr = 0; pr < 4; pr++) {
                int row = wn * 64 + pr * 16 + (lane & 7) + ((lane & 16) >> 1);
                int cch = ks * 2 + ((lane >> 3) & 1);
                unsigned ad = sB + row * 128 + ((cch ^ (row & 7)) << 4);
                asm volatile("ldmatrix.sync.aligned.m8n8.x4.shared.b16 {%0,%1,%2,%3}, [%4];\n"
                             : "=r"(bq[pr][0]), "=r"(bq[pr][1]), "=r"(bq[pr][2]), "=r"(bq[pr][3])
                             : "r"(ad));
            }
#pragma unroll
            for (int mt = 0; mt < 2; mt++)
#pragma unroll
                for (int nt = 0; nt < 8; nt++) {
                    unsigned b0 = bq[nt >> 1][(nt & 1) * 2];
                    unsigned b1 = bq[nt >> 1][(nt & 1) * 2 + 1];
                    asm volatile(
                        "mma.sync.aligned.m16n8k16.row.col.f32.bf16.bf16.f32 "
                        "{%0,%1,%2,%3}, {%4,%5,%6,%7}, {%8,%9}, {%0,%1,%2,%3};\n"
                        : "+f"(acc[mt][nt][0]), "+f"(acc[mt][nt][1]),
                          "+f"(acc[mt][nt][2]), "+f"(acc[mt][nt][3])
                        : "r"(af[mt][0]), "r"(af[mt][1]), "r"(af[mt][2]), "r"(af[mt][3]),
                          "r"(b0), "r"(b1));
                }
        }
    }

    // epilogue: rows 0-255 -> g_score, rows 256-511 -> g_sims (bm is tile of 128)
    float* outBase = (bm < 2) ? (g_score + (size_t)bm * BM * PP)
                              : (g_sims + (size_t)(bm - 2) * BM * PP);
    int g = lane >> 2, tg = lane & 3;
#pragma unroll
    for (int mt = 0; mt < 2; mt++) {
        int m0 = wm * 32 + mt * 16 + g;
#pragma unroll
        for (int nt = 0; nt < 8; nt++) {
            int n = bn * BN + wn * 64 + nt * 8 + tg * 2;
            *(float2*)(outBase + (size_t)m0 * PP + n) =
                make_float2(acc[mt][nt][0], acc[mt][nt][1]);
            *(float2*)(outBase + (size_t)(m0 + 8) * PP + n) =
                make_float2(acc[mt][nt][2], acc[mt][nt][3]);
        }
    }
}

// ---------------- radix top-K helpers ----------------
__device__ __forceinline__ unsigned f2key(float v) {
    unsigned u = __float_as_uint(v);
    return (u & 0x80000000u) ? ~u : (u | 0x80000000u);
}
__device__ __forceinline__ float key2f(unsigned u) {
    unsigned b = (u & 0x80000000u) ? (u ^ 0x80000000u) : ~u;
    return __uint_as_float(b);
}

// ---------------- merged loss kernel (512 blocks: 0-255 off, 256-511 on) ----------------
__global__ __launch_bounds__(256) void loss_kernel() {
    __shared__ unsigned keys[PP];        // 32 KB
    __shared__ unsigned hist[256];
    __shared__ unsigned sfx[257];
    __shared__ float    fval[BGKNN + NPP];
    __shared__ int      idxl[BGKNN];
    __shared__ int      boost[KPOS];
    __shared__ unsigned ck[256];
    __shared__ int      ci[256];
    __shared__ unsigned sh[4];           // 0:prefix 1:rem 2:eqcnt 3:outcnt

    const int bx = blockIdx.x;
    const int mode = bx >> 8;            // 0 = offline, 1 = online
    const int row = bx & 255;
    const int t = threadIdx.x;

    if (mode == 0) {
        const float* src = g_score + (size_t)row * PP;
        const int p0 = g_py[row] * NPP;
        for (int p = t; p < PP; p += 256) {
            unsigned u = f2key(src[p]);
            keys[p] = ((unsigned)(p - p0) < 8u) ? 0u : u;     // mask positives
        }
        __syncthreads();
    } else {
        const float* ssrc = g_sims + (size_t)row * PP;
        unsigned bk = 0; int bi = 0x7fffffff;
        for (int p = t; p < PP; p += 256) {
            unsigned u = f2key(ssrc[p]);
            keys[p] = u;
            if (u > bk) { bk = u; bi = p >> 3; }              // cam = p & 7 == t & 7
        }
        ck[t] = bk; ci[t] = bi;
        __syncthreads();
        for (int s = 128; s >= 8; s >>= 1) {
            if (t < s) {
                unsigned ok = ck[t + s]; int oi = ci[t + s];
                if (ok > ck[t] || (ok == ck[t] && oi < ci[t])) { ck[t] = ok; ci[t] = oi; }
            }
            __syncthreads();
        }
        if (t == 0) {
            bool used[NCAMS] = {};
            for (int j = 0; j < KPOS; j++) {
                int bc = -1; unsigned bv = 0;
                for (int c = 0; c < NCAMS; c++)
                    if (!used[c] && (bc < 0 || ck[c] > bv)) { bc = c; bv = ck[c]; }
                used[bc] = true;
                int proxy = ci[bc] * NCAMS + bc;
                boost[j] = proxy;
                keys[proxy] = 0u;        // exclude from background top-40
            }
        }
        __syncthreads();
    }

    // ---- 4-pass radix select of top BGKNN ----
    unsigned prefix = 0; int rem = BGKNN;
    for (int pass = 0; pass < 4; pass++) {
        const int shift = 24 - 8 * pass;
        hist[t] = 0;
        __syncthreads();
        const unsigned mask = pass ? (0xFFFFFFFFu << (shift + 8)) : 0u;
        for (int p = t; p < PP; p += 256) {
            unsigned u = keys[p];
            if ((u & mask) == prefix) {
                unsigned d = (u >> shift) & 255u;
                unsigned am = __activemask();
                unsigned mm = __match_any_sync(am, d);
                if ((int)(t & 31) == __ffs(mm) - 1) atomicAdd(&hist[d], __popc(mm));
            }
        }
        __syncthreads();
        // inclusive suffix sum of hist (Hillis-Steele)
        unsigned v = hist[t];
        sfx[t] = v;
        if (t == 0) sfx[256] = 0;
        __syncthreads();
        for (int off = 1; off < 256; off <<= 1) {
            unsigned add = (t + off < 256) ? sfx[t + off] : 0;
            __syncthreads();
            v += add; sfx[t] = v;
            __syncthreads();
        }
        unsigned nxt = sfx[t + 1];
        if (sfx[t] >= (unsigned)rem && nxt < (unsigned)rem) {
            sh[0] = prefix | ((unsigned)t << shift);
            sh[1] = (unsigned)(rem - (int)nxt);
        }
        __syncthreads();
        prefix = sh[0]; rem = (int)sh[1];
        __syncthreads();
    }
    const unsigned T = prefix;
    const int need = rem;
    if (t == 0) { sh[2] = 0; sh[3] = 0; }
    __syncthreads();

    // ---- collect top-40 ----
    for (int p = t; p < PP; p += 256) {
        unsigned u = keys[p];
        if (u > T) {
            unsigned s2 = atomicAdd(&sh[3], 1u);
            if (mode == 0) fval[s2] = key2f(u); else idxl[s2] = p;
        } else if (u == T) {
            unsigned e = atomicAdd(&sh[2], 1u);
            if (e < (unsigned)need) {
                unsigned s2 = atomicAdd(&sh[3], 1u);
                if (mode == 0) fval[s2] = key2f(u); else idxl[s2] = p;
            }
        }
    }
    __syncthreads();

    // ---- gather values + positives ----
    if (mode == 0) {
        if (t < NPP) {
            const float* src = g_score + (size_t)row * PP;
            fval[BGKNN + t] = src[g_py[row] * NPP + t];
        }
    } else {
        const float* inp = g_score + (size_t)row * PP;   // values come from inputs!
        if (t < BGKNN) fval[t] = inp[idxl[t]];
        else if (t < BGKNN + KPOS) fval[t] = inp[boost[t - BGKNN]];
    }
    __syncthreads();

    // ---- log-sum-exp loss by warp 0 ----
    if (t < 32) {
        const int K = mode ? (BGKNN + KPOS) : (BGKNN + NPP);
        const int pcnt = mode ? KPOS : NPP;
        float a = (t < K) ? fval[t] * 10.0f : -1e30f;
        float b = (t + 32 < K) ? fval[t + 32] * 10.0f : -1e30f;
        float m = fmaxf(a, b);
#pragma unroll
        for (int o = 16; o; o >>= 1) m = fmaxf(m, __shfl_xor_sync(0xffffffffu, m, o));
        float e = 0.f, ps = 0.f;
        if (t < K) e += __expf(a - m);
        if (t + 32 < K) e += __expf(b - m);
        if (t + 32 >= BGKNN && t + 32 < BGKNN + pcnt) ps = b;
#pragma unroll
        for (int o = 16; o; o >>= 1) {
            e += __shfl_xor_sync(0xffffffffu, e, o);
            ps += __shfl_xor_sync(0xffffffffu, ps, o);
        }
        if (t == 0) {
            float L = m + logf(e) - ps / (float)pcnt;
            if (mode) g_Lon[row] = L; else g_Loff[row] = L;
        }
    }
}

// ---------------- deterministic parallel finalize ----------------
__global__ void finalize_kernel(float* out) {
    __shared__ float lo[BB], ln[BB];
    __shared__ int cm[BB];
    __shared__ float acc[NCAMS];
    int t = threadIdx.x;
    lo[t] = g_Loff[t]; ln[t] = g_Lon[t]; cm[t] = g_camArr[t];
    __syncthreads();
    if (t < NCAMS) {
        float so = 0.f, sn = 0.f; int n = 0;
        for (int i = 0; i < BB; i++)
            if (cm[i] == t) { so += lo[i]; sn += ln[i]; n++; }
        acc[t] = (n > 0) ? (so / n + sn / n) : 0.f;
    }
    __syncthreads();
    if (t == 0) {
        float L = 0.f;
        for (int c = 0; c < NCAMS; c++) L += acc[c];
        out[0] = L;
    }
}

// ---------------- launch ----------------
extern "C" void kernel_launch(void* const* d_in, const int* in_sizes, int n_in,
                              void* d_out, int out_size) {
    const float* features = (const float*)d_in[0];
    const float* gmemory  = (const float*)d_in[1];
    const int*   targets  = (const int*)d_in[2];
    const int*   apl      = (const int*)d_in[3];
    float* out = (float*)d_out;

    prep_meta_kernel<<<1, 256>>>(targets, apl);
    convB_kernel<<<(PP * DD / 4 + 255) / 256, 256>>>(gmemory);
    buildA_kernel<<<(MTOT * DD / 4 + 255) / 256, 256>>>(features, gmemory);

    cudaFuncSetAttribute(gemm_kernel, cudaFuncAttributeMaxDynamicSharedMemorySize,
                         GEMM_SMEM);
    gemm_kernel<<<dim3(PP / BN, MTOT / BM), 256, GEMM_SMEM>>>();

    loss_kernel<<<2 * BB, 256>>>();
    finalize_kernel<<<1, 256>>>(out);
}